// round 1
// baseline (speedup 1.0000x reference)
#include <cuda_runtime.h>
#include <math.h>
#include <stdint.h>

#define D 256
#define MAXN 16384
#define MAXK 8192

// scratch (no allocation allowed)
__device__ float g_A[MAXN];      // per-row sum z^2
__device__ float g_C[MAXK];      // per-code sum c^2
__device__ int   g_idx[MAXN];    // argmin index per row
__device__ float g_rowss[MAXN];  // per-row sum d^2 (for loss)

// ---------------- A = sum(z*z) per row, sequential fp32 order ----------------
__global__ void k_rowsumA(const float* __restrict__ z, int n) {
    int r = blockIdx.x * blockDim.x + threadIdx.x;
    if (r >= n) return;
    const float4* p = reinterpret_cast<const float4*>(z + (size_t)r * D);
    float a = 0.f;
#pragma unroll 8
    for (int i = 0; i < D / 4; ++i) {
        float4 v = p[i];
        a = __fadd_rn(a, __fmul_rn(v.x, v.x));
        a = __fadd_rn(a, __fmul_rn(v.y, v.y));
        a = __fadd_rn(a, __fmul_rn(v.z, v.z));
        a = __fadd_rn(a, __fmul_rn(v.w, v.w));
    }
    g_A[r] = a;
}

// ---------------- C = sum(c*c) per code ----------------
__global__ void k_colsumC(const float* __restrict__ cb, int K) {
    int r = blockIdx.x * blockDim.x + threadIdx.x;
    if (r >= K) return;
    const float4* p = reinterpret_cast<const float4*>(cb + (size_t)r * D);
    float a = 0.f;
#pragma unroll 8
    for (int i = 0; i < D / 4; ++i) {
        float4 v = p[i];
        a = __fadd_rn(a, __fmul_rn(v.x, v.x));
        a = __fadd_rn(a, __fmul_rn(v.y, v.y));
        a = __fadd_rn(a, __fmul_rn(v.z, v.z));
        a = __fadd_rn(a, __fmul_rn(v.w, v.w));
    }
    g_C[r] = a;
}

// ---------------- argmin over codes: fused GEMM + argmin ----------------
// BM=64 rows per CTA, BN=128 codes per chunk, 256 threads,
// thread tile TM=4 rows x TN=8 codes. k-major smem tiles, sequential-k FMA.
#define BM 64
#define BN 128
#define ZS_STRIDE 68    // (BM + 4) pad, floats
#define CS_STRIDE 132   // (BN + 4) pad, floats

__global__ __launch_bounds__(256, 2)
void k_argmin(const float* __restrict__ z, const float* __restrict__ cb,
              int n, int K) {
    extern __shared__ float sm[];
    float* zsm = sm;                       // [256][ZS_STRIDE] k-major z tile
    float* csm = sm + 256 * ZS_STRIDE;     // [64][CS_STRIDE]  k-major code tile

    const int tid = threadIdx.x;
    const int tx = tid & 15;       // code group (8 codes)
    const int ty = tid >> 4;       // row group  (4 rows)
    const int ty4 = ty * 4;
    const int tx8 = tx * 8;
    const int row0 = blockIdx.x * BM;

    // load 64 z rows transposed -> zsm[k][r]
    const float4* zg4 = reinterpret_cast<const float4*>(z);
    for (int idx = tid; idx < BM * (D / 4); idx += 256) {
        int r  = idx >> 6;     // 0..63
        int k4 = idx & 63;     // 0..63
        float4 v = zg4[(size_t)(row0 + r) * (D / 4) + k4];
        float* b = zsm + (k4 * 4) * ZS_STRIDE + r;
        b[0] = v.x; b[ZS_STRIDE] = v.y; b[2 * ZS_STRIDE] = v.z; b[3 * ZS_STRIDE] = v.w;
    }

    float Areg[4];
#pragma unroll
    for (int i = 0; i < 4; ++i) Areg[i] = g_A[row0 + ty4 + i];

    float bestv[4];
    int   besti[4];
#pragma unroll
    for (int i = 0; i < 4; ++i) { bestv[i] = 3.4e38f; besti[i] = 0; }

    const float4* cg4 = reinterpret_cast<const float4*>(cb);
    const int nchunks = K / BN;

    for (int cc = 0; cc < nchunks; ++cc) {
        float acc[4][8];
#pragma unroll
        for (int i = 0; i < 4; ++i)
#pragma unroll
            for (int j = 0; j < 8; ++j) acc[i][j] = 0.f;

        for (int kc = 0; kc < 4; ++kc) {
            __syncthreads();
            // load BN codes x 64 k, transposed -> csm[kk][code]
            for (int idx = tid; idx < BN * 16; idx += 256) {
                int code = idx >> 4;   // 0..127
                int k4   = idx & 15;   // 0..15
                float4 v = cg4[(size_t)(cc * BN + code) * (D / 4) + kc * 16 + k4];
                float* b = csm + (k4 * 4) * CS_STRIDE + code;
                b[0] = v.x; b[CS_STRIDE] = v.y; b[2 * CS_STRIDE] = v.z; b[3 * CS_STRIDE] = v.w;
            }
            __syncthreads();

#pragma unroll 16
            for (int kk = 0; kk < 64; ++kk) {
                const int k = kc * 64 + kk;
                float4 zf = *reinterpret_cast<const float4*>(zsm + k * ZS_STRIDE + ty4);
                float4 c0 = *reinterpret_cast<const float4*>(csm + kk * CS_STRIDE + tx8);
                float4 c1 = *reinterpret_cast<const float4*>(csm + kk * CS_STRIDE + tx8 + 4);
                float zr[4] = { zf.x, zf.y, zf.z, zf.w };
                float cr[8] = { c0.x, c0.y, c0.z, c0.w, c1.x, c1.y, c1.z, c1.w };
#pragma unroll
                for (int i = 0; i < 4; ++i)
#pragma unroll
                    for (int j = 0; j < 8; ++j)
                        acc[i][j] = __fmaf_rn(zr[i], cr[j], acc[i][j]);
            }
        }

        // score + argmin update (codes ascending -> first-index tie-break via strict <)
#pragma unroll
        for (int j = 0; j < 8; ++j) {
            const int code = cc * BN + tx8 + j;
            const float Cc = __ldg(&g_C[code]);
#pragma unroll
            for (int i = 0; i < 4; ++i) {
                float s = __fadd_rn(__fmaf_rn(-2.f, acc[i][j], Areg[i]), Cc);
                if (s < bestv[i]) { bestv[i] = s; besti[i] = code; }
            }
        }
    }

    // reduce across the 16 code-groups (reuse csm)
    __syncthreads();
    float* rv = csm;                        // 64*16 floats
    int*   ri = (int*)(csm + BM * 16);      // 64*16 ints
#pragma unroll
    for (int i = 0; i < 4; ++i) {
        rv[(ty4 + i) * 16 + tx] = bestv[i];
        ri[(ty4 + i) * 16 + tx] = besti[i];
    }
    __syncthreads();
    if (tid < BM) {
        float bv = rv[tid * 16];
        int   bi = ri[tid * 16];
        for (int t = 1; t < 16; ++t) {
            float v = rv[tid * 16 + t];
            int  ix = ri[tid * 16 + t];
            if (v < bv || (v == bv && ix < bi)) { bv = v; bi = ix; }
        }
        g_idx[row0 + tid] = bi;
    }
}

// ---------------- finish: gather, z_q, per-row d^2, indices ----------------
__global__ void k_finish(const float* __restrict__ z, const float* __restrict__ cb,
                         float* __restrict__ zq, float* __restrict__ idxout) {
    const int row = blockIdx.x;
    const int t = threadIdx.x;          // 128 threads, 2 elems each
    const int code = g_idx[row];
    const float2 zp = reinterpret_cast<const float2*>(z + (size_t)row * D)[t];
    const float2 cp = reinterpret_cast<const float2*>(cb + (size_t)code * D)[t];
    float d0 = __fsub_rn(cp.x, zp.x);
    float d1 = __fsub_rn(cp.y, zp.y);
    float ss = __fadd_rn(__fmul_rn(d0, d0), __fmul_rn(d1, d1));

    __shared__ float red[4];
#pragma unroll
    for (int o = 16; o > 0; o >>= 1)
        ss = __fadd_rn(ss, __shfl_xor_sync(0xffffffffu, ss, o));
    if ((t & 31) == 0) red[t >> 5] = ss;
    __syncthreads();
    float ssum = __fadd_rn(__fadd_rn(red[0], red[1]), __fadd_rn(red[2], red[3]));

    float mag = __fsqrt_rn(ssum);
    float den = __fadd_rn(mag, 1e-8f);
    float q0 = __fadd_rn(zp.x, __fmul_rn(mag, __fdiv_rn(d0, den)));
    float q1 = __fadd_rn(zp.y, __fmul_rn(mag, __fdiv_rn(d1, den)));
    float2 o; o.x = q0; o.y = q1;
    reinterpret_cast<float2*>(zq + (size_t)row * D)[t] = o;
    if (t == 0) {
        g_rowss[row] = ssum;
        idxout[row] = (float)code;
    }
}

// ---------------- loss = 1.25 * mean(d^2) ----------------
__global__ void k_loss(float* __restrict__ out_loss, int n) {
    __shared__ double sred[256];
    double s = 0.0;
    for (int i = threadIdx.x; i < n; i += 256) s += (double)g_rowss[i];
    sred[threadIdx.x] = s;
    __syncthreads();
    for (int o = 128; o > 0; o >>= 1) {
        if (threadIdx.x < o) sred[threadIdx.x] += sred[threadIdx.x + o];
        __syncthreads();
    }
    if (threadIdx.x == 0) {
        double mean = sred[0] / ((double)n * (double)D);
        out_loss[0] = (float)(1.25 * mean);
    }
}

extern "C" void kernel_launch(void* const* d_in, const int* in_sizes, int n_in,
                              void* d_out, int out_size) {
    const float* z  = (const float*)d_in[0];
    const float* cb = (const float*)d_in[1];
    const int n = in_sizes[0] / D;   // 16384
    const int K = in_sizes[1] / D;   // 8192

    float* out    = (float*)d_out;
    float* zq     = out;
    float* loss   = out + (size_t)n * D;
    float* idxout = loss + 1;

    k_rowsumA<<<(n + 255) / 256, 256>>>(z, n);
    k_colsumC<<<(K + 255) / 256, 256>>>(cb, K);

    const int smem = (256 * ZS_STRIDE + 64 * CS_STRIDE) * (int)sizeof(float); // 103424
    static bool attr_set = false;
    // idempotent attribute set (not a stream op; safe under capture)
    cudaFuncSetAttribute(k_argmin, cudaFuncAttributeMaxDynamicSharedMemorySize, smem);
    (void)attr_set;

    k_argmin<<<n / BM, 256, smem>>>(z, cb, n, K);
    k_finish<<<n, 128>>>(z, cb, zq, idxout);
    k_loss<<<1, 256>>>(loss, n);
}

// round 3
// speedup vs baseline: 5.7164x; 5.7164x over previous
#include <cuda_runtime.h>
#include <cuda_bf16.h>
#include <stdint.h>
#include <math.h>

#define D 256
#define MAXN 16384
#define MAXK 8192

// ---------------- scratch (module globals; no runtime allocation) ----------------
__device__ float          g_C[MAXK];          // per-code sum c^2
__device__ int            g_cand[MAXN * 4];   // top-4 candidates per row
__device__ int            g_idx[MAXN];        // final argmin per row
__device__ float          g_rowss[MAXN];      // per-row sum d^2
__device__ __nv_bfloat16  g_zb[MAXN * D];     // bf16 copy of z
__device__ __nv_bfloat16  g_cbb[MAXK * D];    // bf16 copy of codebook

// ================= tiny PTX helpers (all sm_80-legal) =================
__device__ __forceinline__ void cpa16(uint32_t dst, const void* src) {
    asm volatile("cp.async.cg.shared.global [%0], [%1], 16;" :: "r"(dst), "l"(src) : "memory");
}
#define CP_COMMIT() asm volatile("cp.async.commit_group;" ::: "memory")
#define CP_WAIT(n)  asm volatile("cp.async.wait_group %0;" :: "n"(n) : "memory")

__device__ __forceinline__ uint32_t smem_u32(const void* p) {
    uint32_t a;
    asm("{ .reg .u64 t; cvta.to.shared.u64 t, %1; cvt.u32.u64 %0, t; }" : "=r"(a) : "l"(p));
    return a;
}

// D += A(16x16 bf16, row-major) * B(16x8, codes row-major = col-major KxN)
__device__ __forceinline__ void mma_bf16(float c[4], const uint32_t a[4], uint32_t b0, uint32_t b1) {
    asm volatile(
        "mma.sync.aligned.m16n8k16.row.col.f32.bf16.bf16.f32 "
        "{%0,%1,%2,%3}, {%4,%5,%6,%7}, {%8,%9}, {%0,%1,%2,%3};"
        : "+f"(c[0]), "+f"(c[1]), "+f"(c[2]), "+f"(c[3])
        : "r"(a[0]), "r"(a[1]), "r"(a[2]), "r"(a[3]), "r"(b0), "r"(b1));
}

// ================= f32 -> bf16 conversion =================
__global__ void k_cvt(const float* __restrict__ src, __nv_bfloat16* __restrict__ dst, int n4) {
    int i = blockIdx.x * blockDim.x + threadIdx.x;
    if (i >= n4) return;
    float4 v = reinterpret_cast<const float4*>(src)[i];
    __nv_bfloat162 h0 = __floats2bfloat162_rn(v.x, v.y);
    __nv_bfloat162 h1 = __floats2bfloat162_rn(v.z, v.w);
    reinterpret_cast<__nv_bfloat162*>(dst)[i * 2]     = h0;
    reinterpret_cast<__nv_bfloat162*>(dst)[i * 2 + 1] = h1;
}

// ================= stage 1: HMMA bf16 GEMM + per-row top-4 =================
// CTA: 128 rows x all K codes, K-chunks of 128 codes. 256 threads = 8 warps (4M x 2N).
// smem rows padded to 528B (132 words) -> fragment LDS bank = (4g+tg)%32, conflict-free.
#define PADW 132
#define PADB 528
#define SM_A  0
#define SM_B0 67584
#define SM_B1 135168
#define SM_TOT 202752

__global__ __launch_bounds__(256, 1)
void k_gemm_topk(int K) {
    extern __shared__ char sm[];
    const uint32_t sb = smem_u32(sm);
    const uint32_t* smw = reinterpret_cast<const uint32_t*>(sm);
    const int tid = threadIdx.x;
    const int lid = tid & 31, wid = tid >> 5;
    const int warpM = wid & 3, warpN = wid >> 1 & 0 ? 0 : (wid >> 2); // warpN = wid>>2
    const int g = lid >> 2, tg = lid & 3;
    const int row0 = blockIdx.x * 128;
    const int nchunks = K / 128;   // 64

    // ---- load A (128 rows x 256 bf16) via cp.async ----
    {
        const __nv_bfloat16* zsrc = g_zb + (size_t)row0 * D;
#pragma unroll
        for (int t = 0; t < 16; ++t) {
            int e = t * 256 + tid;          // 0..4095
            int r = e >> 5, j = e & 31;     // row, 16B-chunk
            cpa16(sb + SM_A + r * PADB + j * 16, zsrc + (size_t)r * D + j * 8);
        }
    }
    // ---- prefetch B chunk 0 ----
    {
        const __nv_bfloat16* csrc = g_cbb;
#pragma unroll
        for (int t = 0; t < 16; ++t) {
            int e = t * 256 + tid;
            int r = e >> 5, j = e & 31;
            cpa16(sb + SM_B0 + r * PADB + j * 16, csrc + (size_t)r * D + j * 8);
        }
    }
    CP_COMMIT();

    // per-thread top-4 for each of its 4 tracked rows
    float bv[4][4];
    int   bi[4][4];
#pragma unroll
    for (int i = 0; i < 4; ++i)
#pragma unroll
        for (int j = 0; j < 4; ++j) { bv[i][j] = -3.4e38f; bi[i][j] = 0; }

    const int aW0 = (SM_A / 4) + (warpM * 32 + g) * PADW + tg;

    for (int i = 0; i < nchunks; ++i) {
        const int s = i & 1;
        if (i + 1 < nchunks) {
            const int sn = (i + 1) & 1;
            const __nv_bfloat16* csrc = g_cbb + (size_t)(i + 1) * 128 * D;
            const uint32_t dstb = sb + (sn ? SM_B1 : SM_B0);
#pragma unroll
            for (int t = 0; t < 16; ++t) {
                int e = t * 256 + tid;
                int r = e >> 5, j = e & 31;
                cpa16(dstb + r * PADB + j * 16, csrc + (size_t)r * D + j * 8);
            }
            CP_COMMIT();
            CP_WAIT(1);
        } else {
            CP_WAIT(0);
        }
        __syncthreads();

        const int bufW = (s ? SM_B1 : SM_B0) / 4;
        float acc[2][8][4];
#pragma unroll
        for (int mt = 0; mt < 2; ++mt)
#pragma unroll
            for (int nt = 0; nt < 8; ++nt)
#pragma unroll
                for (int q = 0; q < 4; ++q) acc[mt][nt][q] = 0.f;

#pragma unroll
        for (int ks = 0; ks < 16; ++ks) {
            uint32_t a[2][4];
#pragma unroll
            for (int mt = 0; mt < 2; ++mt) {
                const int base = aW0 + mt * 16 * PADW + ks * 8;
                a[mt][0] = smw[base];                 // row g,   k-lo
                a[mt][1] = smw[base + 8 * PADW];      // row g+8, k-lo
                a[mt][2] = smw[base + 4];             // row g,   k-hi
                a[mt][3] = smw[base + 8 * PADW + 4];  // row g+8, k-hi
            }
#pragma unroll
            for (int nt = 0; nt < 8; ++nt) {
                const int bb = bufW + (warpN * 64 + nt * 8 + g) * PADW + ks * 8 + tg;
                uint32_t b0 = smw[bb];
                uint32_t b1 = smw[bb + 4];
                mma_bf16(acc[0][nt], a[0], b0, b1);
                mma_bf16(acc[1][nt], a[1], b0, b1);
            }
        }

        // ---- top-4 update ----
        const int cbase0 = i * 128 + warpN * 64 + tg * 2;
#pragma unroll
        for (int mt = 0; mt < 2; ++mt) {
#pragma unroll
            for (int nt = 0; nt < 8; ++nt) {
                const int gc = cbase0 + nt * 8;
#pragma unroll
                for (int q = 0; q < 4; ++q) {
                    const int tr = mt * 2 + (q >> 1);          // row slot
                    const float v = acc[mt][nt][q];
                    const int ci = gc + (q & 1);
                    if (v > bv[tr][3]) {
                        if (v > bv[tr][0]) {
                            bv[tr][3]=bv[tr][2]; bi[tr][3]=bi[tr][2];
                            bv[tr][2]=bv[tr][1]; bi[tr][2]=bi[tr][1];
                            bv[tr][1]=bv[tr][0]; bi[tr][1]=bi[tr][0];
                            bv[tr][0]=v; bi[tr][0]=ci;
                        } else if (v > bv[tr][1]) {
                            bv[tr][3]=bv[tr][2]; bi[tr][3]=bi[tr][2];
                            bv[tr][2]=bv[tr][1]; bi[tr][2]=bi[tr][1];
                            bv[tr][1]=v; bi[tr][1]=ci;
                        } else if (v > bv[tr][2]) {
                            bv[tr][3]=bv[tr][2]; bi[tr][3]=bi[tr][2];
                            bv[tr][2]=v; bi[tr][2]=ci;
                        } else {
                            bv[tr][3]=v; bi[tr][3]=ci;
                        }
                    }
                }
            }
        }
        __syncthreads();
    }

    // ---- merge: 8 owners x top4 per row -> global top4 ----
    // reuse A region: vals 16KB @ sm, idxs 16KB @ sm+16384
    float* mv = reinterpret_cast<float*>(sm);
    int*   mi = reinterpret_cast<int*>(sm + 16384);
    const int owner = warpN * 4 + tg;
#pragma unroll
    for (int tr = 0; tr < 4; ++tr) {
        const int srow = warpM * 32 + (tr >> 1) * 16 + (tr & 1) * 8 + g;
#pragma unroll
        for (int j = 0; j < 4; ++j) {
            mv[(srow * 8 + owner) * 4 + j] = bv[tr][j];
            mi[(srow * 8 + owner) * 4 + j] = bi[tr][j];
        }
    }
    __syncthreads();
    if (tid < 128) {
        float fv0=-3.4e38f, fv1=-3.4e38f, fv2=-3.4e38f, fv3=-3.4e38f;
        int   fi0=0, fi1=0, fi2=0, fi3=0;
        for (int e = 0; e < 32; ++e) {
            float v = mv[tid * 32 + e];
            int  ci = mi[tid * 32 + e];
            if (v > fv3) {
                if (v > fv0)      { fv3=fv2;fi3=fi2; fv2=fv1;fi2=fi1; fv1=fv0;fi1=fi0; fv0=v;fi0=ci; }
                else if (v > fv1) { fv3=fv2;fi3=fi2; fv2=fv1;fi2=fi1; fv1=v;fi1=ci; }
                else if (v > fv2) { fv3=fv2;fi3=fi2; fv2=v;fi2=ci; }
                else              { fv3=v;fi3=ci; }
            }
        }
        const int r = row0 + tid;
        g_cand[r * 4 + 0] = fi0;
        g_cand[r * 4 + 1] = fi1;
        g_cand[r * 4 + 2] = fi2;
        g_cand[r * 4 + 3] = fi3;
    }
}

// ================= C = sum(c*c) per code (exact, matches R1) =================
__global__ void k_colsumC(const float* __restrict__ cb, int K) {
    int r = blockIdx.x * blockDim.x + threadIdx.x;
    if (r >= K) return;
    const float4* p = reinterpret_cast<const float4*>(cb + (size_t)r * D);
    float a = 0.f;
#pragma unroll 8
    for (int i = 0; i < D / 4; ++i) {
        float4 v = p[i];
        a = __fadd_rn(a, __fmul_rn(v.x, v.x));
        a = __fadd_rn(a, __fmul_rn(v.y, v.y));
        a = __fadd_rn(a, __fmul_rn(v.z, v.z));
        a = __fadd_rn(a, __fmul_rn(v.w, v.w));
    }
    g_C[r] = a;
}

// ================= stage 2: exact fp32 rescore of 4 candidates =================
// Bit-identical arithmetic to the R1 full scan: sequential-k fmaf dot,
// fl(A-2B)+C, min by (value, index).
__global__ void k_rescore(const float* __restrict__ z, const float* __restrict__ cb, int n) {
    int row = blockIdx.x * blockDim.x + threadIdx.x;
    if (row >= n) return;
    const float4* zr = reinterpret_cast<const float4*>(z + (size_t)row * D);

    float A = 0.f;
#pragma unroll 8
    for (int i = 0; i < D / 4; ++i) {
        float4 v = zr[i];
        A = __fadd_rn(A, __fmul_rn(v.x, v.x));
        A = __fadd_rn(A, __fmul_rn(v.y, v.y));
        A = __fadd_rn(A, __fmul_rn(v.z, v.z));
        A = __fadd_rn(A, __fmul_rn(v.w, v.w));
    }

    float bestv = 3.4e38f;
    int   besti = 0x7fffffff;
#pragma unroll
    for (int m = 0; m < 4; ++m) {
        const int c = g_cand[row * 4 + m];
        const float4* cr = reinterpret_cast<const float4*>(cb + (size_t)c * D);
        float acc = 0.f;
#pragma unroll 8
        for (int i = 0; i < D / 4; ++i) {
            float4 a = zr[i];
            float4 b = cr[i];
            acc = __fmaf_rn(a.x, b.x, acc);
            acc = __fmaf_rn(a.y, b.y, acc);
            acc = __fmaf_rn(a.z, b.z, acc);
            acc = __fmaf_rn(a.w, b.w, acc);
        }
        float s = __fadd_rn(__fmaf_rn(-2.f, acc, A), g_C[c]);
        if (s < bestv || (s == bestv && c < besti)) { bestv = s; besti = c; }
    }
    g_idx[row] = besti;
}

// ================= finish: gather, z_q, per-row d^2, indices =================
__global__ void k_finish(const float* __restrict__ z, const float* __restrict__ cb,
                         float* __restrict__ zq, float* __restrict__ idxout) {
    const int row = blockIdx.x;
    const int t = threadIdx.x;          // 128 threads, 2 elems each
    const int code = g_idx[row];
    const float2 zp = reinterpret_cast<const float2*>(z + (size_t)row * D)[t];
    const float2 cp = reinterpret_cast<const float2*>(cb + (size_t)code * D)[t];
    float d0 = __fsub_rn(cp.x, zp.x);
    float d1 = __fsub_rn(cp.y, zp.y);
    float ss = __fadd_rn(__fmul_rn(d0, d0), __fmul_rn(d1, d1));

    __shared__ float red[4];
#pragma unroll
    for (int o = 16; o > 0; o >>= 1)
        ss = __fadd_rn(ss, __shfl_xor_sync(0xffffffffu, ss, o));
    if ((t & 31) == 0) red[t >> 5] = ss;
    __syncthreads();
    float ssum = __fadd_rn(__fadd_rn(red[0], red[1]), __fadd_rn(red[2], red[3]));

    float mag = __fsqrt_rn(ssum);
    float den = __fadd_rn(mag, 1e-8f);
    float q0 = __fadd_rn(zp.x, __fmul_rn(mag, __fdiv_rn(d0, den)));
    float q1 = __fadd_rn(zp.y, __fmul_rn(mag, __fdiv_rn(d1, den)));
    float2 o; o.x = q0; o.y = q1;
    reinterpret_cast<float2*>(zq + (size_t)row * D)[t] = o;
    if (t == 0) {
        g_rowss[row] = ssum;
        idxout[row] = (float)code;
    }
}

// ================= loss = 1.25 * mean(d^2) =================
__global__ void k_loss(float* __restrict__ out_loss, int n) {
    __shared__ double sred[256];
    double s = 0.0;
    for (int i = threadIdx.x; i < n; i += 256) s += (double)g_rowss[i];
    sred[threadIdx.x] = s;
    __syncthreads();
    for (int o = 128; o > 0; o >>= 1) {
        if (threadIdx.x < o) sred[threadIdx.x] += sred[threadIdx.x + o];
        __syncthreads();
    }
    if (threadIdx.x == 0) {
        double mean = sred[0] / ((double)n * (double)D);
        out_loss[0] = (float)(1.25 * mean);
    }
}

extern "C" void kernel_launch(void* const* d_in, const int* in_sizes, int n_in,
                              void* d_out, int out_size) {
    const float* z  = (const float*)d_in[0];
    const float* cb = (const float*)d_in[1];
    const int n = in_sizes[0] / D;   // 16384
    const int K = in_sizes[1] / D;   // 8192

    float* out    = (float*)d_out;
    float* zq     = out;
    float* loss   = out + (size_t)n * D;
    float* idxout = loss + 1;

    cudaFuncSetAttribute(k_gemm_topk, cudaFuncAttributeMaxDynamicSharedMemorySize, SM_TOT);

    __nv_bfloat16* zb;  cudaGetSymbolAddress((void**)&zb,  g_zb);
    __nv_bfloat16* cbb; cudaGetSymbolAddress((void**)&cbb, g_cbb);

    k_cvt<<<(n * D / 4 + 255) / 256, 256>>>(z,  zb,  n * D / 4);
    k_cvt<<<(K * D / 4 + 255) / 256, 256>>>(cb, cbb, K * D / 4);
    k_colsumC<<<(K + 255) / 256, 256>>>(cb, K);
    k_gemm_topk<<<n / 128, 256, SM_TOT>>>(K);
    k_rescore<<<(n + 255) / 256, 256>>>(z, cb, n);
    k_finish<<<n, 128>>>(z, cb, zq, idxout);
    k_loss<<<1, 256>>>(loss, n);
}

// round 4
// speedup vs baseline: 6.6880x; 1.1700x over previous
#include <cuda_runtime.h>
#include <cuda_bf16.h>
#include <stdint.h>
#include <math.h>

#define D 256
#define MAXN 16384
#define MAXK 8192

// ---------------- scratch (module globals; no runtime allocation) ----------------
__device__ float          g_C[MAXK];          // per-code sum c^2
__device__ int            g_cand[MAXN * 4];   // top-4 candidates per row
__device__ int            g_idx[MAXN];        // final argmin per row
__device__ float          g_rowss[MAXN];      // per-row sum d^2
__device__ __nv_bfloat16  g_zb[MAXN * D];     // bf16 copy of z
__device__ __nv_bfloat16  g_cbb[MAXK * D];    // bf16 copy of codebook

// ================= tiny PTX helpers (all sm_80-legal) =================
__device__ __forceinline__ void cpa16(uint32_t dst, const void* src) {
    asm volatile("cp.async.cg.shared.global [%0], [%1], 16;" :: "r"(dst), "l"(src) : "memory");
}
#define CP_COMMIT() asm volatile("cp.async.commit_group;" ::: "memory")
#define CP_WAIT(n)  asm volatile("cp.async.wait_group %0;" :: "n"(n) : "memory")

__device__ __forceinline__ uint32_t smem_u32(const void* p) {
    uint32_t a;
    asm("{ .reg .u64 t; cvta.to.shared.u64 t, %1; cvt.u32.u64 %0, t; }" : "=r"(a) : "l"(p));
    return a;
}
__device__ __forceinline__ void ldsm_x4(uint32_t r[4], uint32_t addr) {
    asm volatile("ldmatrix.sync.aligned.m8n8.x4.shared.b16 {%0,%1,%2,%3}, [%4];"
        : "=r"(r[0]), "=r"(r[1]), "=r"(r[2]), "=r"(r[3]) : "r"(addr));
}
__device__ __forceinline__ void ldsm_x2(uint32_t r[2], uint32_t addr) {
    asm volatile("ldmatrix.sync.aligned.m8n8.x2.shared.b16 {%0,%1}, [%2];"
        : "=r"(r[0]), "=r"(r[1]) : "r"(addr));
}
// D += A(16x16 bf16, row-major) * B(16x8 col-major)
__device__ __forceinline__ void mma_bf16(float c[4], const uint32_t a[4], uint32_t b0, uint32_t b1) {
    asm volatile(
        "mma.sync.aligned.m16n8k16.row.col.f32.bf16.bf16.f32 "
        "{%0,%1,%2,%3}, {%4,%5,%6,%7}, {%8,%9}, {%0,%1,%2,%3};"
        : "+f"(c[0]), "+f"(c[1]), "+f"(c[2]), "+f"(c[3])
        : "r"(a[0]), "r"(a[1]), "r"(a[2]), "r"(a[3]), "r"(b0), "r"(b1));
}

// ================= f32 -> bf16 conversion =================
__global__ void k_cvt(const float* __restrict__ src, __nv_bfloat16* __restrict__ dst, int n4) {
    int i = blockIdx.x * blockDim.x + threadIdx.x;
    if (i >= n4) return;
    float4 v = reinterpret_cast<const float4*>(src)[i];
    __nv_bfloat162 h0 = __floats2bfloat162_rn(v.x, v.y);
    __nv_bfloat162 h1 = __floats2bfloat162_rn(v.z, v.w);
    reinterpret_cast<__nv_bfloat162*>(dst)[i * 2]     = h0;
    reinterpret_cast<__nv_bfloat162*>(dst)[i * 2 + 1] = h1;
}

// ================= stage 1: HMMA bf16 GEMM + per-row top-4 =================
// CTA: 128 rows x all K codes, chunks of 128 codes. 512 threads = 16 warps (4M x 4N).
// Warp tile 32 rows x 32 codes. smem rows padded to 528B -> conflict-free LDSM.
#define PADW 132
#define PADB 528
#define SM_A  0
#define SM_B0 67584
#define SM_B1 135168
#define SM_TOT 202752

__global__ __launch_bounds__(512, 1)
void k_gemm_topk(int K) {
    extern __shared__ char sm[];
    const uint32_t sb = smem_u32(sm);
    const int tid = threadIdx.x;
    const int lid = tid & 31, wid = tid >> 5;
    const int warpM = wid & 3, warpN = wid >> 2;
    const int g = lid >> 2, tg = lid & 3;
    const int row0 = blockIdx.x * 128;
    const int nchunks = K / 128;   // 64

    // ---- load A (128 rows x 256 bf16) via cp.async ----
    {
        const __nv_bfloat16* zsrc = g_zb + (size_t)row0 * D;
#pragma unroll
        for (int t = 0; t < 8; ++t) {
            int e = t * 512 + tid;          // 0..4095
            int r = e >> 5, j = e & 31;
            cpa16(sb + SM_A + r * PADB + j * 16, zsrc + (size_t)r * D + j * 8);
        }
    }
    // ---- prefetch B chunk 0 ----
    {
#pragma unroll
        for (int t = 0; t < 8; ++t) {
            int e = t * 512 + tid;
            int r = e >> 5, j = e & 31;
            cpa16(sb + SM_B0 + r * PADB + j * 16, g_cbb + (size_t)r * D + j * 8);
        }
    }
    CP_COMMIT();

    // ldmatrix lane address components
    const int aLane = (lid & 15);
    const int aKoff = (lid >> 4) * 16;
    const int bLane = (lid & 7);
    const int bKoff = ((lid >> 3) & 1) * 16;
    // A fragment base addresses (per mt), advance by 32B per k-step
    uint32_t aAddr[2];
#pragma unroll
    for (int mt = 0; mt < 2; ++mt)
        aAddr[mt] = sb + SM_A + (uint32_t)(warpM * 32 + mt * 16 + aLane) * PADB + aKoff;

    // per-thread top-4 for each of its 4 tracked rows
    float bv[4][4];
    int   bi[4][4];
#pragma unroll
    for (int i = 0; i < 4; ++i)
#pragma unroll
        for (int j = 0; j < 4; ++j) { bv[i][j] = -3.4e38f; bi[i][j] = 0; }

    for (int i = 0; i < nchunks; ++i) {
        const int s = i & 1;
        if (i + 1 < nchunks) {
            const int sn = (i + 1) & 1;
            const __nv_bfloat16* csrc = g_cbb + (size_t)(i + 1) * 128 * D;
            const uint32_t dstb = sb + (sn ? SM_B1 : SM_B0);
#pragma unroll
            for (int t = 0; t < 8; ++t) {
                int e = t * 512 + tid;
                int r = e >> 5, j = e & 31;
                cpa16(dstb + r * PADB + j * 16, csrc + (size_t)r * D + j * 8);
            }
            CP_COMMIT();
            CP_WAIT(1);
        } else {
            CP_WAIT(0);
        }
        __syncthreads();

        uint32_t bBase[4];
#pragma unroll
        for (int nt = 0; nt < 4; ++nt)
            bBase[nt] = sb + (s ? SM_B1 : SM_B0)
                      + (uint32_t)(warpN * 32 + nt * 8 + bLane) * PADB + bKoff;

        float acc[2][4][4];
#pragma unroll
        for (int mt = 0; mt < 2; ++mt)
#pragma unroll
            for (int nt = 0; nt < 4; ++nt)
#pragma unroll
                for (int q = 0; q < 4; ++q) acc[mt][nt][q] = 0.f;

#pragma unroll
        for (int ks = 0; ks < 16; ++ks) {
            uint32_t a[2][4];
            ldsm_x4(a[0], aAddr[0] + ks * 32);
            ldsm_x4(a[1], aAddr[1] + ks * 32);
#pragma unroll
            for (int nt = 0; nt < 4; ++nt) {
                uint32_t b[2];
                ldsm_x2(b, bBase[nt] + ks * 32);
                mma_bf16(acc[0][nt], a[0], b[0], b[1]);
                mma_bf16(acc[1][nt], a[1], b[0], b[1]);
            }
        }

        // ---- top-4 update ----
        const int cbase0 = i * 128 + warpN * 32 + tg * 2;
#pragma unroll
        for (int mt = 0; mt < 2; ++mt) {
#pragma unroll
            for (int nt = 0; nt < 4; ++nt) {
                const int gc = cbase0 + nt * 8;
#pragma unroll
                for (int q = 0; q < 4; ++q) {
                    const int tr = mt * 2 + (q >> 1);
                    const float v = acc[mt][nt][q];
                    const int ci = gc + (q & 1);
                    if (v > bv[tr][3]) {
                        if (v > bv[tr][0]) {
                            bv[tr][3]=bv[tr][2]; bi[tr][3]=bi[tr][2];
                            bv[tr][2]=bv[tr][1]; bi[tr][2]=bi[tr][1];
                            bv[tr][1]=bv[tr][0]; bi[tr][1]=bi[tr][0];
                            bv[tr][0]=v; bi[tr][0]=ci;
                        } else if (v > bv[tr][1]) {
                            bv[tr][3]=bv[tr][2]; bi[tr][3]=bi[tr][2];
                            bv[tr][2]=bv[tr][1]; bi[tr][2]=bi[tr][1];
                            bv[tr][1]=v; bi[tr][1]=ci;
                        } else if (v > bv[tr][2]) {
                            bv[tr][3]=bv[tr][2]; bi[tr][3]=bi[tr][2];
                            bv[tr][2]=v; bi[tr][2]=ci;
                        } else {
                            bv[tr][3]=v; bi[tr][3]=ci;
                        }
                    }
                }
            }
        }
        __syncthreads();
    }

    // ---- merge: 16 owners x top4 per row -> global top4 (reuse A region) ----
    float* mv = reinterpret_cast<float*>(sm);           // 128*16*4 floats = 32KB
    int*   mi = reinterpret_cast<int*>(sm + 32768);     // 32KB
    const int owner = warpN * 4 + tg;                   // 0..15
#pragma unroll
    for (int tr = 0; tr < 4; ++tr) {
        const int srow = warpM * 32 + (tr >> 1) * 16 + (tr & 1) * 8 + g;
#pragma unroll
        for (int j = 0; j < 4; ++j) {
            mv[srow * 64 + owner * 4 + j] = bv[tr][j];
            mi[srow * 64 + owner * 4 + j] = bi[tr][j];
        }
    }
    __syncthreads();
    if (tid < 128) {
        float fv0=-3.4e38f, fv1=-3.4e38f, fv2=-3.4e38f, fv3=-3.4e38f;
        int   fi0=0, fi1=0, fi2=0, fi3=0;
        for (int e = 0; e < 64; ++e) {
            float v = mv[tid * 64 + e];
            int  ci = mi[tid * 64 + e];
            if (v > fv3) {
                if (v > fv0)      { fv3=fv2;fi3=fi2; fv2=fv1;fi2=fi1; fv1=fv0;fi1=fi0; fv0=v;fi0=ci; }
                else if (v > fv1) { fv3=fv2;fi3=fi2; fv2=fv1;fi2=fi1; fv1=v;fi1=ci; }
                else if (v > fv2) { fv3=fv2;fi3=fi2; fv2=v;fi2=ci; }
                else              { fv3=v;fi3=ci; }
            }
        }
        const int r = row0 + tid;
        g_cand[r * 4 + 0] = fi0;
        g_cand[r * 4 + 1] = fi1;
        g_cand[r * 4 + 2] = fi2;
        g_cand[r * 4 + 3] = fi3;
    }
}

// ================= C = sum(c*c) per code (exact, matches R1) =================
__global__ void k_colsumC(const float* __restrict__ cb, int K) {
    int r = blockIdx.x * blockDim.x + threadIdx.x;
    if (r >= K) return;
    const float4* p = reinterpret_cast<const float4*>(cb + (size_t)r * D);
    float a = 0.f;
#pragma unroll 8
    for (int i = 0; i < D / 4; ++i) {
        float4 v = p[i];
        a = __fadd_rn(a, __fmul_rn(v.x, v.x));
        a = __fadd_rn(a, __fmul_rn(v.y, v.y));
        a = __fadd_rn(a, __fmul_rn(v.z, v.z));
        a = __fadd_rn(a, __fmul_rn(v.w, v.w));
    }
    g_C[r] = a;
}

// ================= stage 2: exact fp32 rescore of 4 candidates =================
__global__ void k_rescore(const float* __restrict__ z, const float* __restrict__ cb, int n) {
    int row = blockIdx.x * blockDim.x + threadIdx.x;
    if (row >= n) return;
    const float4* zr = reinterpret_cast<const float4*>(z + (size_t)row * D);

    float A = 0.f;
#pragma unroll 8
    for (int i = 0; i < D / 4; ++i) {
        float4 v = zr[i];
        A = __fadd_rn(A, __fmul_rn(v.x, v.x));
        A = __fadd_rn(A, __fmul_rn(v.y, v.y));
        A = __fadd_rn(A, __fmul_rn(v.z, v.z));
        A = __fadd_rn(A, __fmul_rn(v.w, v.w));
    }

    float bestv = 3.4e38f;
    int   besti = 0x7fffffff;
#pragma unroll
    for (int m = 0; m < 4; ++m) {
        const int c = g_cand[row * 4 + m];
        const float4* cr = reinterpret_cast<const float4*>(cb + (size_t)c * D);
        float acc = 0.f;
#pragma unroll 8
        for (int i = 0; i < D / 4; ++i) {
            float4 a = zr[i];
            float4 b = cr[i];
            acc = __fmaf_rn(a.x, b.x, acc);
            acc = __fmaf_rn(a.y, b.y, acc);
            acc = __fmaf_rn(a.z, b.z, acc);
            acc = __fmaf_rn(a.w, b.w, acc);
        }
        float s = __fadd_rn(__fmaf_rn(-2.f, acc, A), g_C[c]);
        if (s < bestv || (s == bestv && c < besti)) { bestv = s; besti = c; }
    }
    g_idx[row] = besti;
}

// ================= finish: gather, z_q, per-row d^2, indices =================
__global__ void k_finish(const float* __restrict__ z, const float* __restrict__ cb,
                         float* __restrict__ zq, float* __restrict__ idxout) {
    const int row = blockIdx.x;
    const int t = threadIdx.x;          // 128 threads, 2 elems each
    const int code = g_idx[row];
    const float2 zp = reinterpret_cast<const float2*>(z + (size_t)row * D)[t];
    const float2 cp = reinterpret_cast<const float2*>(cb + (size_t)code * D)[t];
    float d0 = __fsub_rn(cp.x, zp.x);
    float d1 = __fsub_rn(cp.y, zp.y);
    float ss = __fadd_rn(__fmul_rn(d0, d0), __fmul_rn(d1, d1));

    __shared__ float red[4];
#pragma unroll
    for (int o = 16; o > 0; o >>= 1)
        ss = __fadd_rn(ss, __shfl_xor_sync(0xffffffffu, ss, o));
    if ((t & 31) == 0) red[t >> 5] = ss;
    __syncthreads();
    float ssum = __fadd_rn(__fadd_rn(red[0], red[1]), __fadd_rn(red[2], red[3]));

    float mag = __fsqrt_rn(ssum);
    float den = __fadd_rn(mag, 1e-8f);
    float q0 = __fadd_rn(zp.x, __fmul_rn(mag, __fdiv_rn(d0, den)));
    float q1 = __fadd_rn(zp.y, __fmul_rn(mag, __fdiv_rn(d1, den)));
    float2 o; o.x = q0; o.y = q1;
    reinterpret_cast<float2*>(zq + (size_t)row * D)[t] = o;
    if (t == 0) {
        g_rowss[row] = ssum;
        idxout[row] = (float)code;
    }
}

// ================= loss = 1.25 * mean(d^2) =================
__global__ void k_loss(float* __restrict__ out_loss, int n) {
    __shared__ double sred[256];
    double s = 0.0;
    for (int i = threadIdx.x; i < n; i += 256) s += (double)g_rowss[i];
    sred[threadIdx.x] = s;
    __syncthreads();
    for (int o = 128; o > 0; o >>= 1) {
        if (threadIdx.x < o) sred[threadIdx.x] += sred[threadIdx.x + o];
        __syncthreads();
    }
    if (threadIdx.x == 0) {
        double mean = sred[0] / ((double)n * (double)D);
        out_loss[0] = (float)(1.25 * mean);
    }
}

extern "C" void kernel_launch(void* const* d_in, const int* in_sizes, int n_in,
                              void* d_out, int out_size) {
    const float* z  = (const float*)d_in[0];
    const float* cb = (const float*)d_in[1];
    const int n = in_sizes[0] / D;   // 16384
    const int K = in_sizes[1] / D;   // 8192

    float* out    = (float*)d_out;
    float* zq     = out;
    float* loss   = out + (size_t)n * D;
    float* idxout = loss + 1;

    cudaFuncSetAttribute(k_gemm_topk, cudaFuncAttributeMaxDynamicSharedMemorySize, SM_TOT);

    __nv_bfloat16* zb;  cudaGetSymbolAddress((void**)&zb,  g_zb);
    __nv_bfloat16* cbb; cudaGetSymbolAddress((void**)&cbb, g_cbb);

    k_cvt<<<(n * D / 4 + 255) / 256, 256>>>(z,  zb,  n * D / 4);
    k_cvt<<<(K * D / 4 + 255) / 256, 256>>>(cb, cbb, K * D / 4);
    k_colsumC<<<(K + 255) / 256, 256>>>(cb, K);
    k_gemm_topk<<<n / 128, 512, SM_TOT>>>(K);
    k_rescore<<<(n + 255) / 256, 256>>>(z, cb, n);
    k_finish<<<n, 128>>>(z, cb, zq, idxout);
    k_loss<<<1, 256>>>(loss, n);
}